// round 17
// baseline (speedup 1.0000x reference)
#include <cuda_runtime.h>
#include <cstdint>

// ---------------------------------------------------------------------------
// HQNN: 3x (Dense+tanh -> 4-qubit RX/CNOT circuit), analytic multilinear
// reformulation. R17: two rows per thread packed into f32x2 lanes; all FMA
// math uses fma.rn.f32x2 (SASS FFMA2, 2 rows per instruction); sin/cos of
// tanh-bounded angles (|x|<1) via packed polynomials (no MUFU); constants
// staged pre-duplicated as float2 so one LDCU.64 is a ready packed operand.
// ---------------------------------------------------------------------------

typedef unsigned long long u64;

struct ConstsLayout2 {
    float2 C[3][16][4];   // 192  probe coefficients, duplicated
    float2 W0[16][4];     // 64
    float2 b0[4];
    float2 W1[4][4];
    float2 b1[4];
    float2 W2[4][4];
    float2 b2[4];
    float2 poly[12];      // sin/cos poly coeffs + tanh constants, duplicated
};   // 312 float2 = 624 floats

__device__ float g_stage[624];
__constant__ ConstsLayout2 cK2;

// ------------------------- setup: probe simulations ------------------------

__device__ void rx_apply(float* re, float* im, float ang, int w) {
    float c = cosf(0.5f * ang);
    float s = sinf(0.5f * ang);
    int bit = 1 << w;
    for (int b = 0; b < 16; b++) {
        if (b & bit) continue;
        int b1 = b | bit;
        float r0 = re[b], i0 = im[b], r1 = re[b1], i1 = im[b1];
        re[b]  = c * r0 + s * i1;
        im[b]  = c * i0 - s * r1;
        re[b1] = c * r1 + s * i0;
        im[b1] = c * i1 - s * r0;
    }
}

__device__ void cnot_apply(float* re, float* im, int cw, int tw) {
    int cb = 1 << cw, tb = 1 << tw;
    for (int b = 0; b < 16; b++) {
        if ((b & cb) && !(b & tb)) {
            int b1 = b | tb;
            float t;
            t = re[b]; re[b] = re[b1]; re[b1] = t;
            t = im[b]; im[b] = im[b1]; im[b1] = t;
        }
    }
}

__global__ void hqnn_setup(const float* __restrict__ theta,
                           const float* __restrict__ W0, const float* __restrict__ b0,
                           const float* __restrict__ W1, const float* __restrict__ b1,
                           const float* __restrict__ W2, const float* __restrict__ b2) {
    int t = threadIdx.x;
    if (t < 48) {
        int l = t >> 4;      // hybrid layer 0..2
        int m = t & 15;      // probe mask over 4 wires
        float re[16], im[16];
        #pragma unroll
        for (int i = 0; i < 16; i++) { re[i] = 0.f; im[i] = 0.f; }
        re[0] = 1.f;
        for (int w = 0; w < 4; w++) {
            float a = ((m >> w) & 1) ? 1.57079632679489662f : 0.0f;
            rx_apply(re, im, a, w);
        }
        for (int e = 0; e < 2; e++) {
            for (int w = 0; w < 4; w++)
                rx_apply(re, im, theta[l * 8 + e * 4 + w], w);
            for (int w = 0; w < 4; w++)
                cnot_apply(re, im, w, (w + 1) & 3);
        }
        for (int w = 0; w < 4; w++) {
            float z = 0.f;
            for (int b = 0; b < 16; b++) {
                float p = re[b] * re[b] + im[b] * im[b];
                z += ((b >> w) & 1) ? -p : p;
            }
            int fi = 2 * ((l * 16 + m) * 4 + w);
            g_stage[fi]     = z;
            g_stage[fi + 1] = z;
        }
    }
    // stage weights (duplicated) after the 384 coefficient floats
    for (int i = t; i < 108; i += blockDim.x) {
        float v;
        if (i < 64)       v = W0[i];
        else if (i < 68)  v = b0[i - 64];
        else if (i < 84)  v = W1[i - 68];
        else if (i < 88)  v = b1[i - 84];
        else if (i < 104) v = W2[i - 88];
        else              v = b2[i - 104];
        g_stage[384 + 2 * i]     = v;
        g_stage[384 + 2 * i + 1] = v;
    }
    // poly + tanh constants (duplicated), slots 300..311 -> floats 600..623
    if (t == 0) {
        const float pv[12] = {
            -1.66666667e-1f,   // [0] sin x^3
             8.33333333e-3f,   // [1] sin x^5
            -1.98412698e-4f,   // [2] sin x^7
            -5.0e-1f,          // [3] cos x^2
             4.16666667e-2f,   // [4] cos x^4
            -1.38888889e-3f,   // [5] cos x^6
             2.48015873e-5f,   // [6] cos x^8
             2.88539008178f,   // [7] 2*log2(e)  (for exp(2x) via ex2)
             1.0f,             // [8] one
            -2.0f,             // [9] minus two
             0.0f, 0.0f
        };
        for (int k = 0; k < 12; k++) {
            g_stage[600 + 2 * k]     = pv[k];
            g_stage[600 + 2 * k + 1] = pv[k];
        }
    }
}

// ------------------------------ packed helpers ------------------------------

__device__ __forceinline__ u64 fma2(u64 a, u64 b, u64 c) {
    u64 d;
    asm("fma.rn.f32x2 %0, %1, %2, %3;" : "=l"(d) : "l"(a), "l"(b), "l"(c));
    return d;
}
__device__ __forceinline__ u64 mul2(u64 a, u64 b) {
    u64 d;
    asm("mul.rn.f32x2 %0, %1, %2;" : "=l"(d) : "l"(a), "l"(b));
    return d;
}
__device__ __forceinline__ u64 add2(u64 a, u64 b) {
    u64 d;
    asm("add.rn.f32x2 %0, %1, %2;" : "=l"(d) : "l"(a), "l"(b));
    return d;
}
__device__ __forceinline__ u64 pack2(float lo, float hi) {
    u64 d;
    asm("mov.b64 %0, {%1, %2};" : "=l"(d) : "f"(lo), "f"(hi));
    return d;
}
__device__ __forceinline__ void unpack2(u64 v, float& lo, float& hi) {
    asm("mov.b64 {%0, %1}, %2;" : "=f"(lo), "=f"(hi) : "l"(v));
}
__device__ __forceinline__ float ex2f(float x) {
    float r;
    asm("ex2.approx.f32 %0, %1;" : "=f"(r) : "f"(x));
    return r;
}
__device__ __forceinline__ float rcpf(float x) {
    float r;
    asm("rcp.approx.f32 %0, %1;" : "=f"(r) : "f"(x));
    return r;
}
// load a duplicated constant pair as a packed operand (LDCU.64)
__device__ __forceinline__ u64 ldc2(const float2& ref) {
    return *reinterpret_cast<const u64*>(&ref);
}

// packed tanh of packed pre-activation (2 MUFU per element; rest f32x2)
__device__ __forceinline__ u64 tanh2(u64 a, u64 kexp, u64 one, u64 mtwo) {
    u64 f = mul2(a, kexp);           // 2x * log2(e)
    float flo, fhi;
    unpack2(f, flo, fhi);
    u64 e = pack2(ex2f(flo), ex2f(fhi));   // e^{2x}
    u64 d = add2(e, one);                   // e^{2x}+1
    float dlo, dhi;
    unpack2(d, dlo, dhi);
    u64 r = pack2(rcpf(dlo), rcpf(dhi));
    return fma2(r, mtwo, one);              // 1 - 2/(e^{2x}+1)
}

// packed sin/cos via poly, valid for |x| < 1 (tanh outputs)
__device__ __forceinline__ void sincos2(u64 a, u64& s, u64& c,
                                        u64 S1, u64 S2, u64 S3,
                                        u64 C1, u64 C2, u64 C3, u64 C4,
                                        u64 one) {
    u64 x2 = mul2(a, a);
    u64 p = fma2(S3, x2, S2);
    p = fma2(p, x2, S1);
    p = fma2(p, x2, one);
    s = mul2(p, a);
    u64 q = fma2(C4, x2, C3);
    q = fma2(q, x2, C2);
    q = fma2(q, x2, C1);
    c = fma2(q, x2, one);
}

// packed 4-qubit circuit: h[4] angles (packed 2 rows) -> o[4] Z expvals
__device__ __forceinline__ void qcirc2(const float2 (&C)[16][4],
                                       const u64 (&h)[4], u64 (&o)[4],
                                       u64 S1, u64 S2, u64 S3,
                                       u64 Cc1, u64 Cc2, u64 Cc3, u64 Cc4,
                                       u64 one) {
    u64 s[4], c[4];
    #pragma unroll
    for (int w = 0; w < 4; w++)
        sincos2(h[w], s[w], c[w], S1, S2, S3, Cc1, Cc2, Cc3, Cc4, one);

    // out0: wires {0,1,3}
    {
        u64 p00 = mul2(c[0], c[1]);
        u64 p10 = mul2(s[0], c[1]);
        u64 p01 = mul2(c[0], s[1]);
        u64 p11 = mul2(s[0], s[1]);
        u64 A = mul2(ldc2(C[0][0]), p00);
        A = fma2(ldc2(C[1][0]),  p10, A);
        A = fma2(ldc2(C[2][0]),  p01, A);
        A = fma2(ldc2(C[3][0]),  p11, A);
        u64 Bv = mul2(ldc2(C[8][0]), p00);
        Bv = fma2(ldc2(C[9][0]),  p10, Bv);
        Bv = fma2(ldc2(C[10][0]), p01, Bv);
        Bv = fma2(ldc2(C[11][0]), p11, Bv);
        o[0] = fma2(Bv, s[3], mul2(A, c[3]));
    }
    // out1: wires {0,2,3}
    {
        u64 q00 = mul2(c[2], c[3]);
        u64 q10 = mul2(s[2], c[3]);
        u64 q01 = mul2(c[2], s[3]);
        u64 q11 = mul2(s[2], s[3]);
        u64 A = mul2(ldc2(C[0][1]), q00);
        A = fma2(ldc2(C[4][1]),  q10, A);
        A = fma2(ldc2(C[8][1]),  q01, A);
        A = fma2(ldc2(C[12][1]), q11, A);
        u64 Bv = mul2(ldc2(C[1][1]), q00);
        Bv = fma2(ldc2(C[5][1]),  q10, Bv);
        Bv = fma2(ldc2(C[9][1]),  q01, Bv);
        Bv = fma2(ldc2(C[13][1]), q11, Bv);
        o[1] = fma2(Bv, s[0], mul2(A, c[0]));
    }
    // out2: wires {1,3}
    {
        u64 v = mul2(ldc2(C[0][2]), mul2(c[1], c[3]));
        v = fma2(ldc2(C[2][2]),  mul2(s[1], c[3]), v);
        v = fma2(ldc2(C[8][2]),  mul2(c[1], s[3]), v);
        v = fma2(ldc2(C[10][2]), mul2(s[1], s[3]), v);
        o[2] = v;
    }
    // out3: wires {0,2}
    {
        u64 v = mul2(ldc2(C[0][3]), mul2(c[0], c[2]));
        v = fma2(ldc2(C[1][3]), mul2(s[0], c[2]), v);
        v = fma2(ldc2(C[4][3]), mul2(c[0], s[2]), v);
        v = fma2(ldc2(C[5][3]), mul2(s[0], s[2]), v);
        o[3] = v;
    }
}

// ------------------------------ main kernel --------------------------------

__global__ void __launch_bounds__(128, 6) hqnn_main(const float4* __restrict__ xv,
                                                    float4* __restrict__ out, int B) {
    int r0 = blockIdx.x * 256 + threadIdx.x;
    int r1 = r0 + 128;
    if (r0 >= B) return;
    bool has1 = (r1 < B);

    // hoisted packed constants (LDCU.64, one each)
    const u64 S1  = ldc2(cK2.poly[0]);
    const u64 S2  = ldc2(cK2.poly[1]);
    const u64 S3  = ldc2(cK2.poly[2]);
    const u64 Cc1 = ldc2(cK2.poly[3]);
    const u64 Cc2 = ldc2(cK2.poly[4]);
    const u64 Cc3 = ldc2(cK2.poly[5]);
    const u64 Cc4 = ldc2(cK2.poly[6]);
    const u64 kexp = ldc2(cK2.poly[7]);
    const u64 one  = ldc2(cK2.poly[8]);
    const u64 mtwo = ldc2(cK2.poly[9]);

    // load both rows (front-batched LDG.128), pack into f32x2 lanes
    const float4* p0 = xv + (size_t)r0 * 4;
    const float4* p1 = xv + (size_t)(has1 ? r1 : r0) * 4;
    float4 a0 = p0[0], b0_ = p0[1], c0_ = p0[2], d0 = p0[3];
    float4 a1 = p1[0], b1_ = p1[1], c1_ = p1[2], d1 = p1[3];

    u64 X[16];
    X[0]  = pack2(a0.x, a1.x);  X[1]  = pack2(a0.y, a1.y);
    X[2]  = pack2(a0.z, a1.z);  X[3]  = pack2(a0.w, a1.w);
    X[4]  = pack2(b0_.x, b1_.x); X[5]  = pack2(b0_.y, b1_.y);
    X[6]  = pack2(b0_.z, b1_.z); X[7]  = pack2(b0_.w, b1_.w);
    X[8]  = pack2(c0_.x, c1_.x); X[9]  = pack2(c0_.y, c1_.y);
    X[10] = pack2(c0_.z, c1_.z); X[11] = pack2(c0_.w, c1_.w);
    X[12] = pack2(d0.x, d1.x);  X[13] = pack2(d0.y, d1.y);
    X[14] = pack2(d0.z, d1.z);  X[15] = pack2(d0.w, d1.w);

    // dense0 (16 -> 4)
    u64 acc[4], h[4], o[4];
    #pragma unroll
    for (int j = 0; j < 4; j++) acc[j] = ldc2(cK2.b0[j]);
    #pragma unroll
    for (int i = 0; i < 16; i++) {
        #pragma unroll
        for (int j = 0; j < 4; j++)
            acc[j] = fma2(X[i], ldc2(cK2.W0[i][j]), acc[j]);
    }
    #pragma unroll
    for (int j = 0; j < 4; j++) h[j] = tanh2(acc[j], kexp, one, mtwo);

    qcirc2(cK2.C[0], h, o, S1, S2, S3, Cc1, Cc2, Cc3, Cc4, one);

    // dense1 (4 -> 4)
    #pragma unroll
    for (int j = 0; j < 4; j++) acc[j] = ldc2(cK2.b1[j]);
    #pragma unroll
    for (int i = 0; i < 4; i++) {
        #pragma unroll
        for (int j = 0; j < 4; j++)
            acc[j] = fma2(o[i], ldc2(cK2.W1[i][j]), acc[j]);
    }
    #pragma unroll
    for (int j = 0; j < 4; j++) h[j] = tanh2(acc[j], kexp, one, mtwo);

    qcirc2(cK2.C[1], h, o, S1, S2, S3, Cc1, Cc2, Cc3, Cc4, one);

    // dense2 (4 -> 4)
    #pragma unroll
    for (int j = 0; j < 4; j++) acc[j] = ldc2(cK2.b2[j]);
    #pragma unroll
    for (int i = 0; i < 4; i++) {
        #pragma unroll
        for (int j = 0; j < 4; j++)
            acc[j] = fma2(o[i], ldc2(cK2.W2[i][j]), acc[j]);
    }
    #pragma unroll
    for (int j = 0; j < 4; j++) h[j] = tanh2(acc[j], kexp, one, mtwo);

    qcirc2(cK2.C[2], h, o, S1, S2, S3, Cc1, Cc2, Cc3, Cc4, one);

    // unpack and store
    float o0l, o0h, o1l, o1h, o2l, o2h, o3l, o3h;
    unpack2(o[0], o0l, o0h);
    unpack2(o[1], o1l, o1h);
    unpack2(o[2], o2l, o2h);
    unpack2(o[3], o3l, o3h);
    out[r0] = make_float4(o0l, o1l, o2l, o3l);
    if (has1) out[r1] = make_float4(o0h, o1h, o2h, o3h);
}

// ------------------------------ launch --------------------------------------

extern "C" void kernel_launch(void* const* d_in, const int* in_sizes, int n_in,
                              void* d_out, int out_size) {
    const float* x     = (const float*)d_in[0];
    const float* theta = (const float*)d_in[1];
    const float* W0    = (const float*)d_in[2];
    const float* b0    = (const float*)d_in[3];
    const float* W1    = (const float*)d_in[4];
    const float* b1    = (const float*)d_in[5];
    const float* W2    = (const float*)d_in[6];
    const float* b2    = (const float*)d_in[7];
    int B = in_sizes[0] / 16;

    hqnn_setup<<<1, 128>>>(theta, W0, b0, W1, b1, W2, b2);

    void* stage_ptr = nullptr;
    cudaGetSymbolAddress(&stage_ptr, g_stage);
    cudaMemcpyToSymbolAsync(cK2, stage_ptr, sizeof(ConstsLayout2), 0,
                            cudaMemcpyDeviceToDevice, 0);

    int rowsPerBlock = 256;           // 128 threads x 2 rows
    int blocks = (B + rowsPerBlock - 1) / rowsPerBlock;
    hqnn_main<<<blocks, 128>>>((const float4*)x, (float4*)d_out, B);
}